// round 2
// baseline (speedup 1.0000x reference)
#include <cuda_runtime.h>

#define NN 50000
#define NE 800000
#define DD 128
#define NC 10
#define NG 64

// ---------------- scratch (static device globals; no runtime alloc) --------
__device__ float g_buf0[NN * DD];   // GEMM output y = dis * (h @ W)
__device__ float g_buf1[NN * DD];   // aggregation output h' (relu)
__device__ float g_dis[NN];
__device__ int   g_deg[NN];
__device__ int   g_off[NN + 1];
__device__ int   g_cur[NN];
__device__ int   g_csr[NE];
__device__ float g_pool[NG * DD];
__device__ float g_cnt[NG];
__device__ int   g_anyodd;          // 0 => indices are int64, nonzero => int32

__device__ __forceinline__ int ld_idx(const void* p, long long i, int is64) {
    return is64 ? (int)((const long long*)p)[i] : ((const int*)p)[i];
}

__device__ __forceinline__ unsigned f2t(float x) {
    unsigned r; asm("cvt.rna.tf32.f32 %0, %1;" : "=r"(r) : "f"(x)); return r;
}

// ---------------- setup: zero deg + dtype detect (fused) --------------------
__global__ void k_init(const void* ei) {
    int i = blockIdx.x * blockDim.x + threadIdx.x;
    if (i < NN) g_deg[i] = 0;
    if (blockIdx.x == 0) {
        // int64 indices < 50000 => every odd 32-bit word is 0.
        __shared__ int sm[256];
        int any = 0;
        for (int j = threadIdx.x; j < 4096; j += 256)
            any |= ((const int*)ei)[2 * j + 1];
        sm[threadIdx.x] = any;
        __syncthreads();
        for (int s = 128; s > 0; s >>= 1) {
            if (threadIdx.x < s) sm[threadIdx.x] |= sm[threadIdx.x + s];
            __syncthreads();
        }
        if (threadIdx.x == 0) g_anyodd = sm[0];
    }
}

__global__ void k_deg(const void* ei) {
    int e = blockIdx.x * blockDim.x + threadIdx.x;
    if (e >= NE) return;
    int is64 = (g_anyodd == 0);
    int c = ld_idx(ei, (long long)NE + e, is64);
    atomicAdd(&g_deg[c], 1);
}

// single-block exclusive scan of g_deg -> g_off/g_cur ; also dis = rsqrt(deg+1)
__global__ void k_scan() {
    __shared__ int sm[1024];
    int t = threadIdx.x;
    const int SEG = (NN + 1023) / 1024;  // 49
    int s0 = t * SEG;
    int s1 = min(s0 + SEG, NN);
    int local = 0;
    for (int i = s0; i < s1; i++) local += g_deg[i];
    sm[t] = local;
    __syncthreads();
    for (int off = 1; off < 1024; off <<= 1) {
        int v = (t >= off) ? sm[t - off] : 0;
        __syncthreads();
        sm[t] += v;
        __syncthreads();
    }
    int run = sm[t] - local;  // exclusive prefix
    for (int i = s0; i < s1; i++) {
        int d = g_deg[i];
        g_off[i] = run;
        g_cur[i] = run;
        g_dis[i] = rsqrtf((float)(d + 1));  // +1 self-loop
        run += d;
    }
    if (t == 1023) g_off[NN] = sm[1023];
}

__global__ void k_scatter(const void* ei) {
    int e = blockIdx.x * blockDim.x + threadIdx.x;
    if (e >= NE) return;
    int is64 = (g_anyodd == 0);
    int r = ld_idx(ei, e, is64);
    int c = ld_idx(ei, (long long)NE + e, is64);
    int pos = atomicAdd(&g_cur[c], 1);
    g_csr[pos] = r;
}

// ---------------- TF32 tensor-core GEMM: Y = dis .* (A @ W) -----------------
// 3-term hi/lo split: a*b ~= al*bh + ah*bl + ah*bh  (fp32-class accuracy)
// A [NN,128], W [128,128], Y = g_buf0. layer==0: A=x_ext, layer==1: A=g_buf1.
#define BM 128
#define BK 16

#define MMA3(ACC, A4, B2)                                                     \
    asm volatile(                                                             \
        "mma.sync.aligned.m16n8k8.row.col.f32.tf32.tf32.f32 "                 \
        "{%0,%1,%2,%3}, {%4,%5,%6,%7}, {%8,%9}, {%0,%1,%2,%3};"               \
        : "+f"(ACC[0]), "+f"(ACC[1]), "+f"(ACC[2]), "+f"(ACC[3])              \
        : "r"(A4[0]), "r"(A4[1]), "r"(A4[2]), "r"(A4[3]),                     \
          "r"(B2[0]), "r"(B2[1]));

__global__ void __launch_bounds__(256, 2) k_gemm(const float* __restrict__ x_ext,
                                                 const float* __restrict__ W,
                                                 int layer) {
    // A: [m][k] stride 20 -> banks (20m+k)%32 all distinct within a warp read
    // B: [k][n] stride 136 -> banks (8k+n)%32 all distinct
    __shared__ unsigned Ah[BM][20], Al[BM][20];
    __shared__ unsigned Bh[BK][136], Bl[BK][136];

    const float* __restrict__ A = (layer == 0) ? x_ext : g_buf1;
    float* __restrict__ Y = g_buf0;

    int t = threadIdx.x;
    int m0 = blockIdx.x * BM;
    int wid = t >> 5, lane = t & 31;
    int wm = (wid >> 2) * 64;   // warp row offset (2 warp-rows)
    int wn = (wid & 3) * 32;    // warp col offset (4 warp-cols)
    int gp = lane >> 2;         // groupID 0..7
    int tig = lane & 3;         // thread-in-group 0..3

    float acc[4][4][4];
#pragma unroll
    for (int i = 0; i < 4; i++)
#pragma unroll
        for (int j = 0; j < 4; j++)
#pragma unroll
            for (int q = 0; q < 4; q++) acc[i][j][q] = 0.f;

    for (int k0 = 0; k0 < DD; k0 += BK) {
        // load A chunk [128 m x 16 k]: 512 float4, 2 per thread
#pragma unroll
        for (int q = 0; q < 2; q++) {
            int id = q * 256 + t;         // 0..511
            int r = id >> 2;              // 0..127
            int c4 = id & 3;              // 0..3 (float4 within 16 k)
            int gm = m0 + r;
            float4 v = make_float4(0.f, 0.f, 0.f, 0.f);
            if (gm < NN) v = *(const float4*)&A[(size_t)gm * DD + k0 + c4 * 4];
            float f[4] = {v.x, v.y, v.z, v.w};
#pragma unroll
            for (int j = 0; j < 4; j++) {
                unsigned h = f2t(f[j]);
                float lo = f[j] - __uint_as_float(h);
                Ah[r][c4 * 4 + j] = h;
                Al[r][c4 * 4 + j] = f2t(lo);
            }
        }
        // load W chunk [16 k x 128 n]: 512 float4
#pragma unroll
        for (int q = 0; q < 2; q++) {
            int id = q * 256 + t;
            int kr = id >> 5;             // 0..15
            int c4 = id & 31;             // 0..31
            float4 v = *(const float4*)&W[(size_t)(k0 + kr) * DD + c4 * 4];
            float f[4] = {v.x, v.y, v.z, v.w};
#pragma unroll
            for (int j = 0; j < 4; j++) {
                unsigned h = f2t(f[j]);
                float lo = f[j] - __uint_as_float(h);
                Bh[kr][c4 * 4 + j] = h;
                Bl[kr][c4 * 4 + j] = f2t(lo);
            }
        }
        __syncthreads();

#pragma unroll
        for (int ks = 0; ks < 2; ks++) {
            int k8 = ks * 8;
            unsigned ah[4][4], al[4][4];
#pragma unroll
            for (int tm = 0; tm < 4; tm++) {
                int row = wm + tm * 16 + gp;
                ah[tm][0] = Ah[row][k8 + tig];
                ah[tm][1] = Ah[row + 8][k8 + tig];
                ah[tm][2] = Ah[row][k8 + tig + 4];
                ah[tm][3] = Ah[row + 8][k8 + tig + 4];
                al[tm][0] = Al[row][k8 + tig];
                al[tm][1] = Al[row + 8][k8 + tig];
                al[tm][2] = Al[row][k8 + tig + 4];
                al[tm][3] = Al[row + 8][k8 + tig + 4];
            }
#pragma unroll
            for (int tn = 0; tn < 4; tn++) {
                int col = wn + tn * 8 + gp;
                unsigned bh[2], bl[2];
                bh[0] = Bh[k8 + tig][col];
                bh[1] = Bh[k8 + tig + 4][col];
                bl[0] = Bl[k8 + tig][col];
                bl[1] = Bl[k8 + tig + 4][col];
#pragma unroll
                for (int tm = 0; tm < 4; tm++) {
                    MMA3(acc[tm][tn], al[tm], bh);   // lo_a * hi_b
                    MMA3(acc[tm][tn], ah[tm], bl);   // hi_a * lo_b
                    MMA3(acc[tm][tn], ah[tm], bh);   // hi_a * hi_b
                }
            }
        }
        __syncthreads();
    }

    // epilogue: Y[m][n] = dis[m] * acc
#pragma unroll
    for (int tm = 0; tm < 4; tm++) {
        int r0 = m0 + wm + tm * 16 + gp;
        int r1 = r0 + 8;
        float d0 = (r0 < NN) ? g_dis[r0] : 0.f;
        float d1 = (r1 < NN) ? g_dis[r1] : 0.f;
#pragma unroll
        for (int tn = 0; tn < 4; tn++) {
            int col = wn + tn * 8 + 2 * tig;
            if (r0 < NN) {
                float2 o = make_float2(d0 * acc[tm][tn][0], d0 * acc[tm][tn][1]);
                *(float2*)&Y[(size_t)r0 * DD + col] = o;
            }
            if (r1 < NN) {
                float2 o = make_float2(d1 * acc[tm][tn][2], d1 * acc[tm][tn][3]);
                *(float2*)&Y[(size_t)r1 * DD + col] = o;
            }
        }
    }
}

// ---------------- aggregation: h' = relu(dis[c]*(y[c]+sum_in y[r]) + b) ----
// in = g_buf0, out = g_buf1. One warp per node; lane owns 4 floats (float4).
__global__ void __launch_bounds__(256) k_agg(const float* __restrict__ bias) {
    int w = (blockIdx.x * blockDim.x + threadIdx.x) >> 5;
    int lane = threadIdx.x & 31;
    if (w >= NN) return;
    const float4* __restrict__ yv = (const float4*)g_buf0;
    float4 a0 = yv[(size_t)w * 32 + lane];  // self-loop contribution y[c]
    float4 a1 = make_float4(0.f, 0.f, 0.f, 0.f);
    float4 a2 = make_float4(0.f, 0.f, 0.f, 0.f);
    float4 a3 = make_float4(0.f, 0.f, 0.f, 0.f);
    int p = g_off[w];
    int e2 = g_off[w + 1];
    for (; p + 3 < e2; p += 4) {
        int r0 = g_csr[p], r1 = g_csr[p + 1], r2 = g_csr[p + 2], r3 = g_csr[p + 3];
        float4 v0 = yv[(size_t)r0 * 32 + lane];
        float4 v1 = yv[(size_t)r1 * 32 + lane];
        float4 v2 = yv[(size_t)r2 * 32 + lane];
        float4 v3 = yv[(size_t)r3 * 32 + lane];
        a0.x += v0.x; a0.y += v0.y; a0.z += v0.z; a0.w += v0.w;
        a1.x += v1.x; a1.y += v1.y; a1.z += v1.z; a1.w += v1.w;
        a2.x += v2.x; a2.y += v2.y; a2.z += v2.z; a2.w += v2.w;
        a3.x += v3.x; a3.y += v3.y; a3.z += v3.z; a3.w += v3.w;
    }
    for (; p < e2; p++) {
        int r0 = g_csr[p];
        float4 v0 = yv[(size_t)r0 * 32 + lane];
        a0.x += v0.x; a0.y += v0.y; a0.z += v0.z; a0.w += v0.w;
    }
    float ds = g_dis[w];
    float4 b = ((const float4*)bias)[lane];
    float4 o;
    o.x = fmaxf(ds * ((a0.x + a1.x) + (a2.x + a3.x)) + b.x, 0.f);
    o.y = fmaxf(ds * ((a0.y + a1.y) + (a2.y + a3.y)) + b.y, 0.f);
    o.z = fmaxf(ds * ((a0.z + a1.z) + (a2.z + a3.z)) + b.z, 0.f);
    o.w = fmaxf(ds * ((a0.w + a1.w) + (a2.w + a3.w)) + b.w, 0.f);
    ((float4*)g_buf1)[(size_t)w * 32 + lane] = o;
}

// ---------------- mean pool per graph (batch is sorted; no atomics) --------
__global__ void k_pool(const void* batch) {
    int g = blockIdx.x;
    int is64 = (g_anyodd == 0);
    int lo = 0, hi = NN;
    while (lo < hi) {
        int mid = (lo + hi) >> 1;
        if (ld_idx(batch, mid, is64) < g) lo = mid + 1; else hi = mid;
    }
    int start = lo;
    hi = NN;
    while (lo < hi) {
        int mid = (lo + hi) >> 1;
        if (ld_idx(batch, mid, is64) <= g) lo = mid + 1; else hi = mid;
    }
    int end = lo;

    int d = threadIdx.x;  // 128 threads, one dim each
    const float* __restrict__ h = g_buf1;
    float s0 = 0.f, s1 = 0.f, s2 = 0.f, s3 = 0.f;
    int i = start;
    for (; i + 3 < end; i += 4) {
        s0 += h[(size_t)i * DD + d];
        s1 += h[(size_t)(i + 1) * DD + d];
        s2 += h[(size_t)(i + 2) * DD + d];
        s3 += h[(size_t)(i + 3) * DD + d];
    }
    for (; i < end; i++) s0 += h[(size_t)i * DD + d];
    g_pool[g * DD + d] = (s0 + s1) + (s2 + s3);
    if (d == 0) g_cnt[g] = (float)(end - start);
}

// ---------------- head: emb @ Wfc + bfc, log_softmax -----------------------
__global__ void k_head(const float* __restrict__ Wfc,
                       const float* __restrict__ bfc,
                       float* __restrict__ out) {
    __shared__ float lg[NG][NC];
    int t = threadIdx.x;            // 640 threads
    int g = t / NC, c = t % NC;
    if (t < NG * NC) {
        float inv = 1.f / fmaxf(g_cnt[g], 1.f);
        float acc = bfc[c];
#pragma unroll 4
        for (int d = 0; d < DD; d++)
            acc += g_pool[g * DD + d] * inv * Wfc[d * NC + c];
        lg[g][c] = acc;
    }
    __syncthreads();
    if (t < NG * NC) {
        float m = -1e30f;
#pragma unroll
        for (int k = 0; k < NC; k++) m = fmaxf(m, lg[g][k]);
        float s = 0.f;
#pragma unroll
        for (int k = 0; k < NC; k++) s += expf(lg[g][k] - m);
        out[g * NC + c] = lg[g][c] - m - logf(s);
    }
}

// ---------------- launch ----------------------------------------------------
extern "C" void kernel_launch(void* const* d_in, const int* in_sizes, int n_in,
                              void* d_out, int out_size) {
    (void)in_sizes; (void)n_in; (void)out_size;
    const float* x   = (const float*)d_in[0];
    const void*  ei  = d_in[1];
    const void*  bat = d_in[2];
    const float* W1  = (const float*)d_in[3];
    const float* b1  = (const float*)d_in[4];
    const float* W2  = (const float*)d_in[5];
    const float* b2  = (const float*)d_in[6];
    const float* Wfc = (const float*)d_in[7];
    const float* bfc = (const float*)d_in[8];
    float* out = (float*)d_out;

    k_init<<<(NN + 255) / 256, 256>>>(ei);
    k_deg<<<(NE + 255) / 256, 256>>>(ei);
    k_scan<<<1, 1024>>>();
    k_scatter<<<(NE + 255) / 256, 256>>>(ei);

    int gblocks = (NN + BM - 1) / BM;
    k_gemm<<<gblocks, 256>>>(x, W1, 0);                 // y1 -> buf0
    k_agg<<<(NN * 32 + 255) / 256, 256>>>(b1);          // h1 -> buf1
    k_gemm<<<gblocks, 256>>>(x, W2, 1);                 // y2 -> buf0 (A=buf1)
    k_agg<<<(NN * 32 + 255) / 256, 256>>>(b2);          // h2 -> buf1

    k_pool<<<NG, DD>>>(bat);
    k_head<<<1, NG * NC>>>(Wfc, bfc, out);
}